// round 5
// baseline (speedup 1.0000x reference)
#include <cuda_runtime.h>
#include <cstdint>

#define D        128
#define NUM_DOW  7
#define NUM_TOD  288
#define NROWS    (NUM_DOW * NUM_TOD)   // 2016
#define RPB      16                    // rows per build block (2016 % 16 == 0)

// Precomputed output rows for every (dow, tod) pair: 2016 * 128 floats = 1 MB.
__device__ float g_table[NROWS * D];

// ---------------------------------------------------------------------------
// Kernel 1: build the 2016-row table.
//   table[row][e] = relu(W1[dow] + W1[7+tod] + b1) dot W2[:, e] + b2[e]
// 126 blocks x 128 threads; each block computes 16 rows, sharing W2 reads.
// ---------------------------------------------------------------------------
__global__ __launch_bounds__(D, 8)
void build_table_kernel(const float* __restrict__ W1,
                        const float* __restrict__ b1,
                        const float* __restrict__ W2,
                        const float* __restrict__ b2) {
    __shared__ float h[RPB][D];

    const int e    = threadIdx.x;        // hidden / output channel 0..127
    const int row0 = blockIdx.x * RPB;

    const float b1e = b1[e];
    #pragma unroll
    for (int r = 0; r < RPB; r++) {
        const int row = row0 + r;
        const int dow = row / NUM_TOD;
        const int tod = row - dow * NUM_TOD;
        const float v = W1[dow * D + e] + W1[(NUM_DOW + tod) * D + e] + b1e;
        h[r][e] = fmaxf(v, 0.0f);
    }
    __syncthreads();

    float acc[RPB];
    const float b2e = b2[e];
    #pragma unroll
    for (int r = 0; r < RPB; r++) acc[r] = b2e;

    #pragma unroll 4
    for (int d = 0; d < D; d++) {
        const float w = W2[d * D + e];          // coalesced; 16-way reuse
        #pragma unroll
        for (int r = 0; r < RPB; r++)
            acc[r] = fmaf(h[r][d], w, acc[r]);  // h[r][d] = smem broadcast
    }

    #pragma unroll
    for (int r = 0; r < RPB; r++)
        g_table[(size_t)(row0 + r) * D + e] = acc[r];
}

// ---------------------------------------------------------------------------
// Kernel 2: gather. One warp per token; each lane moves one float4 (16 B),
// so a warp writes the full 512 B output row coalesced.
// TE is [ntok, 2] **int32** (JAX x64-disabled downcasts int64 -> int32).
// Table (1 MB) stays L2-resident; HBM traffic ~= TE read + 64 MB output write.
// ---------------------------------------------------------------------------
__global__ __launch_bounds__(256, 8)
void gather_kernel(const int2* __restrict__ TE,   // [ntok] pairs (dow_raw, tod_raw)
                   float4* __restrict__ out,      // [ntok, 32] float4
                   int ntok) {
    const int warp = (int)((blockIdx.x * blockDim.x + threadIdx.x) >> 5);
    const int lane = threadIdx.x & 31;
    if (warp >= ntok) return;

    // One 8B load, same address across the warp -> single broadcast.
    const int2 te = __ldg(TE + warp);
    const unsigned dow = (unsigned)te.x % NUM_DOW;
    const unsigned tod = (unsigned)te.y % NUM_TOD;
    const unsigned row = dow * NUM_TOD + tod;

    const float4* __restrict__ trow =
        (const float4*)g_table + (size_t)row * (D / 4);
    out[(size_t)warp * (D / 4) + lane] = trow[lane];
}

// ---------------------------------------------------------------------------
// Inputs (metadata order): TE, T, W1, b1, W2, b2. T unused.
// Output: [B, S, 1, D] float32 — contiguous, identical to [ntok, D].
// ---------------------------------------------------------------------------
extern "C" void kernel_launch(void* const* d_in, const int* in_sizes, int n_in,
                              void* d_out, int out_size) {
    const int2*  TE = (const int2*)d_in[0];
    const float* W1 = (const float*)d_in[2];
    const float* b1 = (const float*)d_in[3];
    const float* W2 = (const float*)d_in[4];
    const float* b2 = (const float*)d_in[5];

    const int ntok = in_sizes[0] / 2;   // B*S = 131072

    build_table_kernel<<<NROWS / RPB, D>>>(W1, b1, W2, b2);

    const int warps_per_block = 256 / 32;
    const int nblocks = (ntok + warps_per_block - 1) / warps_per_block;
    gather_kernel<<<nblocks, 256>>>(TE, (float4*)d_out, ntok);
}

// round 6
// speedup vs baseline: 1.3514x; 1.3514x over previous
#include <cuda_runtime.h>
#include <cstdint>

#define D        128
#define NUM_DOW  7
#define NUM_TOD  288
#define NROWS    (NUM_DOW * NUM_TOD)   // 2016
#define RPB      8                     // rows per build block -> 252 blocks

// Precomputed output rows for every (dow, tod) pair: 2016 * 128 floats = 1 MB.
__device__ float g_table[NROWS * D];

// ---------------------------------------------------------------------------
// Kernel 1: build the 2016-row table.
//   table[row][e] = relu(W1[dow] + W1[7+tod] + b1) dot W2[:, e] + b2[e]
// 252 blocks x 128 threads (>=2 warps/SMSP on most SMs for issue overlap).
// h read back as float4 to quarter the shared-load instruction count.
// ---------------------------------------------------------------------------
__global__ __launch_bounds__(D, 8)
void build_table_kernel(const float* __restrict__ W1,
                        const float* __restrict__ b1,
                        const float* __restrict__ W2,
                        const float* __restrict__ b2) {
    __shared__ __align__(16) float h[RPB][D];

    const int e    = threadIdx.x;        // hidden / output channel 0..127
    const int row0 = blockIdx.x * RPB;

    const float b1e = b1[e];
    #pragma unroll
    for (int r = 0; r < RPB; r++) {
        const int row = row0 + r;
        const int dow = row / NUM_TOD;
        const int tod = row - dow * NUM_TOD;
        const float v = W1[dow * D + e] + W1[(NUM_DOW + tod) * D + e] + b1e;
        h[r][e] = fmaxf(v, 0.0f);
    }
    __syncthreads();

    float acc[RPB];
    const float b2e = b2[e];
    #pragma unroll
    for (int r = 0; r < RPB; r++) acc[r] = b2e;

    const float4* __restrict__ h4 = (const float4*)&h[0][0];  // [RPB][32]

    #pragma unroll 4
    for (int d4 = 0; d4 < D / 4; d4++) {
        // 4 coalesced W2 column loads (stride D between them), L1-resident.
        const float w0 = W2[(4 * d4 + 0) * D + e];
        const float w1 = W2[(4 * d4 + 1) * D + e];
        const float w2 = W2[(4 * d4 + 2) * D + e];
        const float w3 = W2[(4 * d4 + 3) * D + e];
        #pragma unroll
        for (int r = 0; r < RPB; r++) {
            const float4 hv = h4[r * (D / 4) + d4];   // warp-broadcast LDS.128
            acc[r] = fmaf(hv.x, w0, acc[r]);
            acc[r] = fmaf(hv.y, w1, acc[r]);
            acc[r] = fmaf(hv.z, w2, acc[r]);
            acc[r] = fmaf(hv.w, w3, acc[r]);
        }
    }

    #pragma unroll
    for (int r = 0; r < RPB; r++)
        g_table[(size_t)(row0 + r) * D + e] = acc[r];
}

// ---------------------------------------------------------------------------
// Kernel 2: gather, 4 tokens per warp for MLP=4 on the L2 table reads.
// Lanes 0..3 load the 4 TE pairs (int32 pairs), rows broadcast via shfl.
// Each thread then issues 4 independent LDG.128 + 4 STG.128 (512 B/row,
// fully coalesced). ntok = 131072 is a multiple of 4.
// ---------------------------------------------------------------------------
__global__ __launch_bounds__(256, 8)
void gather_kernel(const int2* __restrict__ TE,   // [ntok] (dow_raw, tod_raw)
                   float4* __restrict__ out,      // [ntok, 32] float4
                   int ntok) {
    const int warp = (int)((blockIdx.x * blockDim.x + threadIdx.x) >> 5);
    const int lane = threadIdx.x & 31;
    const int t0   = warp * 4;
    if (t0 >= ntok) return;

    // Lane j (mod 4) computes the row index for token t0+j.
    const int2 te = __ldg(TE + t0 + (lane & 3));
    const unsigned myrow =
        ((unsigned)te.x % NUM_DOW) * NUM_TOD + ((unsigned)te.y % NUM_TOD);

    unsigned rows[4];
    #pragma unroll
    for (int j = 0; j < 4; j++)
        rows[j] = __shfl_sync(0xFFFFFFFFu, myrow, j);

    const float4* __restrict__ tab = (const float4*)g_table;

    float4 v[4];
    #pragma unroll
    for (int j = 0; j < 4; j++)                       // 4 independent L2 reads
        v[j] = __ldg(tab + (size_t)rows[j] * (D / 4) + lane);

    #pragma unroll
    for (int j = 0; j < 4; j++)
        out[(size_t)(t0 + j) * (D / 4) + lane] = v[j];
}

// ---------------------------------------------------------------------------
// Inputs (metadata order): TE, T, W1, b1, W2, b2. T unused.
// Output: [B, S, 1, D] float32 — contiguous, identical to [ntok, D].
// ---------------------------------------------------------------------------
extern "C" void kernel_launch(void* const* d_in, const int* in_sizes, int n_in,
                              void* d_out, int out_size) {
    const int2*  TE = (const int2*)d_in[0];
    const float* W1 = (const float*)d_in[2];
    const float* b1 = (const float*)d_in[3];
    const float* W2 = (const float*)d_in[4];
    const float* b2 = (const float*)d_in[5];

    const int ntok = in_sizes[0] / 2;   // B*S = 131072

    build_table_kernel<<<NROWS / RPB, D>>>(W1, b1, W2, b2);

    // 4 tokens per warp, 8 warps per block -> 32 tokens per block.
    const int nblocks = (ntok + 31) / 32;
    gather_kernel<<<nblocks, 256>>>(TE, (float4*)d_out, ntok);
}

// round 7
// speedup vs baseline: 1.3849x; 1.0247x over previous
#include <cuda_runtime.h>
#include <cstdint>

#define D        128
#define NUM_DOW  7
#define NUM_TOD  288
#define NROWS    (NUM_DOW * NUM_TOD)   // 2016
#define RPB      16                    // rows per build block -> 126 blocks
#define TPW      8                     // tokens per warp in gather

// Precomputed output rows for every (dow, tod) pair: 2016 * 128 floats = 1 MB.
__device__ float g_table[NROWS * D];

// ---------------------------------------------------------------------------
// Kernel 1: build the 2016-row table.
//   table[row][e] = relu(W1[dow] + W1[7+tod] + b1) dot W2[:, e] + b2[e]
// 126 blocks x 256 threads. Thread = (e = tid&127, half = tid>>7).
// Each thread computes 8 rows (its half of the 16-row block).
// W2 columns are read identically by both halves -> 2x L1 reuse; W2 L2
// traffic = 126 * 64KB = 8 MB total.
// ---------------------------------------------------------------------------
__global__ __launch_bounds__(256, 4)
void build_table_kernel(const float* __restrict__ W1,
                        const float* __restrict__ b1,
                        const float* __restrict__ W2,
                        const float* __restrict__ b2) {
    __shared__ __align__(16) float h[RPB][D];

    const int e    = threadIdx.x & (D - 1);   // channel 0..127
    const int half = threadIdx.x >> 7;        // 0 or 1
    const int rbase = half * (RPB / 2);       // my 8 rows within the block
    const int row0 = blockIdx.x * RPB;

    const float b1e = __ldg(b1 + e);
    #pragma unroll
    for (int i = 0; i < RPB / 2; i++) {
        const int r   = rbase + i;
        const int row = row0 + r;
        const int dow = row / NUM_TOD;
        const int tod = row - dow * NUM_TOD;
        const float v = __ldg(W1 + dow * D + e)
                      + __ldg(W1 + (NUM_DOW + tod) * D + e) + b1e;
        h[r][e] = fmaxf(v, 0.0f);
    }
    __syncthreads();

    float acc[RPB / 2];
    const float b2e = __ldg(b2 + e);
    #pragma unroll
    for (int i = 0; i < RPB / 2; i++) acc[i] = b2e;

    const float4* __restrict__ h4 = (const float4*)&h[0][0];  // [RPB][32]

    #pragma unroll 4
    for (int d4 = 0; d4 < D / 4; d4++) {
        // Same 4 w-values for both halves -> L1 hit for the second half.
        const float w0 = __ldg(W2 + (4 * d4 + 0) * D + e);
        const float w1 = __ldg(W2 + (4 * d4 + 1) * D + e);
        const float w2 = __ldg(W2 + (4 * d4 + 2) * D + e);
        const float w3 = __ldg(W2 + (4 * d4 + 3) * D + e);
        #pragma unroll
        for (int i = 0; i < RPB / 2; i++) {
            const float4 hv = h4[(rbase + i) * (D / 4) + d4];  // LDS.128 bcast
            acc[i] = fmaf(hv.x, w0, acc[i]);
            acc[i] = fmaf(hv.y, w1, acc[i]);
            acc[i] = fmaf(hv.z, w2, acc[i]);
            acc[i] = fmaf(hv.w, w3, acc[i]);
        }
    }

    #pragma unroll
    for (int i = 0; i < RPB / 2; i++)
        g_table[(size_t)(row0 + rbase + i) * D + e] = acc[i];
}

// ---------------------------------------------------------------------------
// Kernel 2: gather, 8 tokens per warp (MLP=8 on the L2 table reads).
// Lanes 0..7 (mod 8) load the 8 TE int32-pairs; rows broadcast via shfl.
// Each thread: 8 independent LDG.128 from the table, then 8 STG.128 with
// evict-first hint so the streaming output doesn't evict the 1MB table
// from L2. ntok = 131072 is a multiple of 8.
// ---------------------------------------------------------------------------
__global__ __launch_bounds__(256)
void gather_kernel(const int2* __restrict__ TE,   // [ntok] (dow_raw, tod_raw)
                   float4* __restrict__ out,      // [ntok, 32] float4
                   int ntok) {
    const int warp = (int)((blockIdx.x * blockDim.x + threadIdx.x) >> 5);
    const int lane = threadIdx.x & 31;
    const int t0   = warp * TPW;
    if (t0 >= ntok) return;

    // 8 distinct TE pairs per warp, 4-way broadcast within each address.
    const int2 te = __ldg(TE + t0 + (lane & (TPW - 1)));
    const unsigned myrow =
        ((unsigned)te.x % NUM_DOW) * NUM_TOD + ((unsigned)te.y % NUM_TOD);

    unsigned rows[TPW];
    #pragma unroll
    for (int j = 0; j < TPW; j++)
        rows[j] = __shfl_sync(0xFFFFFFFFu, myrow, j);

    const float4* __restrict__ tab = (const float4*)g_table;

    float4 v[TPW];
    #pragma unroll
    for (int j = 0; j < TPW; j++)                 // 8 independent L2 reads
        v[j] = __ldg(tab + (size_t)rows[j] * (D / 4) + lane);

    #pragma unroll
    for (int j = 0; j < TPW; j++)                 // evict-first streaming store
        __stcs(out + (size_t)(t0 + j) * (D / 4) + lane, v[j]);
}

// ---------------------------------------------------------------------------
// Inputs (metadata order): TE, T, W1, b1, W2, b2. T unused.
// Output: [B, S, 1, D] float32 — contiguous, identical to [ntok, D].
// ---------------------------------------------------------------------------
extern "C" void kernel_launch(void* const* d_in, const int* in_sizes, int n_in,
                              void* d_out, int out_size) {
    const int2*  TE = (const int2*)d_in[0];
    const float* W1 = (const float*)d_in[2];
    const float* b1 = (const float*)d_in[3];
    const float* W2 = (const float*)d_in[4];
    const float* b2 = (const float*)d_in[5];

    const int ntok = in_sizes[0] / 2;   // B*S = 131072

    build_table_kernel<<<NROWS / RPB, 256>>>(W1, b1, W2, b2);

    // 8 tokens/warp, 8 warps/block -> 64 tokens per block.
    const int nblocks = (ntok + 8 * TPW - 1) / (8 * TPW);
    gather_kernel<<<nblocks, 256>>>(TE, (float4*)d_out, ntok);
}